// round 10
// baseline (speedup 1.0000x reference)
#include <cuda_runtime.h>
#include <cuda_bf16.h>
#include <stdint.h>

// Problem constants (TokenSelector: B=32, D=256, H=W=64)
#define BB 32
#define DD 256
#define NN 4096          // H*W
#define KK 2048          // NN * KEEP_RATIO

#define GRP    8                 // batches per pipeline group
#define NGRP   (BB / GRP)        // 4 groups
#define SCORE_BLKS_PER_B 16      // score: 16 blocks x 256 thr per batch
#define GATH_BLKS_PER_B  128     // gather: 128 blocks per batch
#define NSCORE (SCORE_BLKS_PER_B * GRP)   // 128
#define NSEL   (GRP)                      // 8
#define NGATH  (GATH_BLKS_PER_B * GRP)    // 1024

// ---------------- scratch (device globals; no allocation allowed) ----------
__device__ unsigned g_keys[BB * NN];
__device__ int      g_pos [BB * NN];

// float -> monotone-increasing uint key
__device__ __forceinline__ unsigned f2k(float f) {
    unsigned u = __float_as_uint(f);
    return u ^ ((u >> 31) ? 0xFFFFFFFFu : 0x80000000u);
}

// ============================================================================
// ROLE 1: score — per-token ordering key. score = rstd*(dot(x,w')-mu*sum(w'))
// (softmax / norm_b / fc_b are order-irrelevant). Thread owns a quad of 4
// consecutive tokens over a 64-wide d-slice (4 splits); warp reads 512B
// contiguous per LDG.128, 4 batched. (Best measured: ~5.6TB/s read ceiling.)
// smem layout: wsh@0(1KB) r1@1024 r2@5120 r3@9216 (4KB each) rw@13312(1KB)
// ============================================================================
__device__ __forceinline__ void score_role(
    const float* __restrict__ tokens, const float* __restrict__ norm_w,
    const float* __restrict__ fc_w, unsigned* __restrict__ keys,
    int b, int bx, char* sm)
{
    float*  wsh = (float*)sm;
    float4* r1  = (float4*)(sm + 1024);
    float4* r2  = (float4*)(sm + 5120);
    float4* r3  = (float4*)(sm + 9216);
    float*  rw  = (float*)(sm + 13312);

    const int tid   = threadIdx.x;
    const int q     = tid & 63;
    const int split = tid >> 6;

    wsh[tid] = norm_w[tid] * fc_w[tid];
    __syncthreads();

    const int n4 = bx * 64 + q;
    const float4* p = (const float4*)(tokens + (size_t)b * DD * NN) + n4;

    float4 s1 = {0.f,0.f,0.f,0.f}, s2 = s1, sd = s1;
    float  sw = 0.f;
#pragma unroll
    for (int j0 = 0; j0 < 64; j0 += 4) {
        float4 x[4];
#pragma unroll
        for (int jj = 0; jj < 4; ++jj)
            x[jj] = p[(size_t)(split * 64 + j0 + jj) * (NN / 4)];
#pragma unroll
        for (int jj = 0; jj < 4; ++jj) {
            float w = wsh[split * 64 + j0 + jj];
            s1.x += x[jj].x;           s1.y += x[jj].y;
            s1.z += x[jj].z;           s1.w += x[jj].w;
            s2.x += x[jj].x * x[jj].x; s2.y += x[jj].y * x[jj].y;
            s2.z += x[jj].z * x[jj].z; s2.w += x[jj].w * x[jj].w;
            sd.x += x[jj].x * w;       sd.y += x[jj].y * w;
            sd.z += x[jj].z * w;       sd.w += x[jj].w * w;
            sw   += w;
        }
    }
    if (split != 0) {
        r1[split * 64 + q] = s1; r2[split * 64 + q] = s2;
        r3[split * 64 + q] = sd; rw[split * 64 + q] = sw;
    }
    __syncthreads();

    if (split == 0) {
#pragma unroll
        for (int s = 1; s < 4; ++s) {
            float4 a = r1[s * 64 + q], c = r2[s * 64 + q], d = r3[s * 64 + q];
            s1.x += a.x; s1.y += a.y; s1.z += a.z; s1.w += a.w;
            s2.x += c.x; s2.y += c.y; s2.z += c.z; s2.w += c.w;
            sd.x += d.x; sd.y += d.y; sd.z += d.z; sd.w += d.w;
            sw   += rw[s * 64 + q];
        }
        const float inv = 1.0f / (float)DD;
        uint4 kv;
        float mu, var;
        mu = s1.x*inv; var = fmaxf(s2.x*inv - mu*mu, 0.f);
        kv.x = f2k((sd.x - mu*sw) * rsqrtf(var + 1e-5f));
        mu = s1.y*inv; var = fmaxf(s2.y*inv - mu*mu, 0.f);
        kv.y = f2k((sd.y - mu*sw) * rsqrtf(var + 1e-5f));
        mu = s1.z*inv; var = fmaxf(s2.z*inv - mu*mu, 0.f);
        kv.z = f2k((sd.z - mu*sw) * rsqrtf(var + 1e-5f));
        mu = s1.w*inv; var = fmaxf(s2.w*inv - mu*mu, 0.f);
        kv.w = f2k((sd.w - mu*sw) * rsqrtf(var + 1e-5f));
        ((uint4*)keys)[b * (NN / 4) + n4] = kv;
    }
}

// ============================================================================
// ROLE 2: select — per-batch radix-select (KK-th largest) + rank compaction.
// 256 threads, 16 keys/thread in registers. Warp-aggregated histogram,
// parallel suffix-scan bin pick, packed warp-shuffle scan compaction.
// Ties: lowest indices win (lax.top_k semantics).
// smem: hist@0(1KB) wsum@1024(32B) prefix@1056 R@1060
// ============================================================================
__device__ __forceinline__ void select_role(
    const unsigned* __restrict__ keys, int* __restrict__ pos, int b, char* sm)
{
    int*      hist     = (int*)sm;
    int*      wsum     = (int*)(sm + 1024);
    unsigned* s_prefix = (unsigned*)(sm + 1056);
    int*      s_R      = (int*)(sm + 1060);

    const int tid  = threadIdx.x;
    const int lane = tid & 31;
    const int wid  = tid >> 5;        // 0..7

    unsigned k[16];
#pragma unroll
    for (int i = 0; i < 4; ++i) {
        uint4 kv = ((const uint4*)(keys + b * NN))[tid * 4 + i];
        k[i*4+0] = kv.x; k[i*4+1] = kv.y; k[i*4+2] = kv.z; k[i*4+3] = kv.w;
    }
    if (tid == 0) { *s_prefix = 0u; *s_R = KK; }
    __syncthreads();

    unsigned mask = 0u;
    for (int shift = 24; shift >= 0; shift -= 8) {
        hist[tid] = 0;
        __syncthreads();
        const unsigned prefix = *s_prefix;
        const int      R      = *s_R;

#pragma unroll
        for (int j = 0; j < 16; ++j) {
            int bin = ((k[j] & mask) == prefix) ? (int)((k[j] >> shift) & 255u) : 256;
            unsigned mm  = __match_any_sync(0xFFFFFFFFu, bin);
            int      ldr = __ffs(mm) - 1;
            if (lane == ldr && bin < 256)
                atomicAdd(&hist[bin], __popc(mm));
        }
        __syncthreads();

        // suffix count S(bin) = #keys with bin' >= bin within prefix class
        int c = hist[255 - tid];
        int v = c;
#pragma unroll
        for (int o = 1; o < 32; o <<= 1) {
            int t = __shfl_up_sync(0xFFFFFFFFu, v, o);
            if (lane >= o) v += t;
        }
        if (lane == 31) wsum[wid] = v;
        __syncthreads();
        int S = v;
#pragma unroll
        for (int w = 0; w < 7; ++w)
            if (w < wid) S += wsum[w];
        if (S >= R && S - c < R) {                 // unique boundary thread
            *s_prefix = prefix | ((unsigned)(255 - tid) << shift);
            *s_R      = R - (S - c);
        }
        mask |= 255u << shift;
        __syncthreads();
    }
    const unsigned T    = *s_prefix;
    const int      Rfin = *s_R;

    int cg = 0, ce = 0;
#pragma unroll
    for (int j = 0; j < 16; ++j) { cg += (k[j] > T); ce += (k[j] == T); }
    int myv = (cg << 16) | ce;
    int v = myv;
#pragma unroll
    for (int o = 1; o < 32; o <<= 1) {
        int t = __shfl_up_sync(0xFFFFFFFFu, v, o);
        if (lane >= o) v += t;
    }
    if (lane == 31) wsum[wid] = v;
    __syncthreads();
    if (wid == 0 && lane < 8) {
        int t = wsum[lane];
#pragma unroll
        for (int o = 1; o < 8; o <<= 1) {
            int u = __shfl_up_sync(0x000000FFu, t, o);
            if (lane >= o) t += u;
        }
        wsum[lane] = t;
    }
    __syncthreads();
    int pre = v - myv + (wid > 0 ? wsum[wid - 1] : 0);
    int g = pre >> 16;
    int e = pre & 0xFFFF;

    int vals[16];
#pragma unroll
    for (int j = 0; j < 16; ++j) {
        int kp = -1;
        if (k[j] > T)       { kp = g + min(e, Rfin); ++g; }
        else if (k[j] == T) { if (e < Rfin) kp = g + e; ++e; }
        vals[j] = kp;
    }
#pragma unroll
    for (int i = 0; i < 4; ++i) {
        int4 op = { vals[i*4+0], vals[i*4+1], vals[i*4+2], vals[i*4+3] };
        ((int4*)(pos + b * NN))[tid * 4 + i] = op;
    }
}

// ============================================================================
// ROLE 3: gather — streaming compaction. 32 tokens x D in two d-halves,
// 128x33 tile (17KB), float4 loads, conflict-free smem both directions.
// Kept rows written as contiguous 512B half-lines with __stcs.
// smem: tile@0 (16896B), spos@16896 (128B)
// ============================================================================
__device__ __forceinline__ void gather_role(
    const float* __restrict__ tokens, const int* __restrict__ pos,
    float* __restrict__ out, int b, int bx, char* sm)
{
    float (*tile)[33] = (float(*)[33])sm;
    int*   spos       = (int*)(sm + 16896);

    const int tid = threadIdx.x;
    const int n0  = bx * 32;

    if (tid < 32) spos[tid] = pos[b * NN + n0 + tid];

    const int f  = tid & 7;
    const int d0 = tid >> 3;
    const float* base = tokens + (size_t)b * DD * NN + n0 + f * 4;
    float* ob = out + (size_t)b * KK * DD;

    const int kk2 = tid >> 7;
    const int c   = tid & 127;

#pragma unroll
    for (int h = 0; h < 2; ++h) {
        __syncthreads();                      // tile reuse guard + spos vis
#pragma unroll
        for (int j = 0; j < 4; ++j) {
            int d = d0 + j * 32;
            float4 v = *(const float4*)(base + (size_t)(h * 128 + d) * NN);
            tile[d][f * 4 + 0] = v.x;
            tile[d][f * 4 + 1] = v.y;
            tile[d][f * 4 + 2] = v.z;
            tile[d][f * 4 + 3] = v.w;
        }
        __syncthreads();
#pragma unroll
        for (int pair = 0; pair < 16; ++pair) {
            int kk = pair * 2 + kk2;
            int p  = spos[kk];
            if (p >= 0)
                __stcs(&ob[(size_t)p * DD + h * 128 + c], tile[c][kk]);
        }
    }
}

// ============================================================================
// Fused pipeline kernel: blocks dispatch by blockIdx.x range into
// [select sel_g | score score_g | gather gath_g]. Groups are independent
// (dependencies satisfied by launch ordering), so score(g+1) and gather(g)
// run CONCURRENTLY in one grid, blending read-only and read+write DRAM
// streams for higher aggregate bandwidth.
// ============================================================================
__global__ void __launch_bounds__(256)
fused_kernel(const float* __restrict__ tokens,
             const float* __restrict__ norm_w,
             const float* __restrict__ fc_w,
             unsigned*    __restrict__ keys,
             int*         __restrict__ pos,
             float*       __restrict__ out,
             int score_g, int sel_g, int gath_g, int nsel, int nscore)
{
    __shared__ __align__(16) char sm[17408];

    int bidx = blockIdx.x;
    if (bidx < nsel) {
        select_role(keys, pos, sel_g * GRP + bidx, sm);
        return;
    }
    bidx -= nsel;
    if (bidx < nscore) {
        score_role(tokens, norm_w, fc_w, keys,
                   score_g * GRP + (bidx >> 4), bidx & 15, sm);
        return;
    }
    bidx -= nscore;
    gather_role(tokens, pos, out,
                gath_g * GRP + (bidx >> 7), bidx & 127, sm);
}

// ---------------------------------------------------------------------------
extern "C" void kernel_launch(void* const* d_in, const int* in_sizes, int n_in,
                              void* d_out, int out_size)
{
    const float* tokens = (const float*)d_in[0];
    const float* norm_w = (const float*)d_in[1];
    // d_in[2] = norm_b (order-irrelevant constant shift)
    const float* fc_w   = (const float*)d_in[3];
    // d_in[4] = fc_b   (order-irrelevant constant shift)
    float* out = (float*)d_out;

    unsigned* keys;
    int* pos;
    cudaGetSymbolAddress((void**)&keys, g_keys);
    cudaGetSymbolAddress((void**)&pos,  g_pos);

    // Pipeline schedule over NGRP=4 groups, 6 launches:
    //  L0: S0 | L1: S1+Sel0 | L2: S2+Sel1+G0 | L3: S3+Sel2+G1
    //  L4: Sel3+G2 | L5: G3
    const int sc[6] = { 0,  1,  2,  3, -1, -1};
    const int se[6] = {-1,  0,  1,  2,  3, -1};
    const int ga[6] = {-1, -1,  0,  1,  2,  3};

    for (int L = 0; L < 6; ++L) {
        int nsel   = (se[L] >= 0) ? NSEL   : 0;
        int nscore = (sc[L] >= 0) ? NSCORE : 0;
        int ngath  = (ga[L] >= 0) ? NGATH  : 0;
        int grid   = nsel + nscore + ngath;
        fused_kernel<<<grid, 256>>>(tokens, norm_w, fc_w, keys, pos, out,
                                    sc[L], se[L], ga[L], nsel, nscore);
    }
}